// round 1
// baseline (speedup 1.0000x reference)
#include <cuda_runtime.h>
#include <cstdint>
#include <cstddef>

// Problem constants (fixed shapes)
#define S_DIM 2048
#define E_DIM 1024
#define H_NUM 16
#define DH_DIM 64
#define B_NUM 2
#define BH_NUM (B_NUM * H_NUM)     // 32
#define M_ROWS (B_NUM * S_DIM)     // 4096

// Scratch (static __device__ arrays — no allocations allowed)
__device__ float g_q[(size_t)BH_NUM * S_DIM * DH_DIM];     // 16 MB
__device__ float g_k[(size_t)BH_NUM * S_DIM * DH_DIM];     // 16 MB
__device__ float g_v[(size_t)BH_NUM * S_DIM * DH_DIM];     // 16 MB
__device__ float g_ctx[(size_t)M_ROWS * E_DIM];            // 16 MB
__device__ float g_attn[(size_t)BH_NUM * S_DIM * S_DIM];   // 512 MB fallback if attn not in d_out

// ---------------------------------------------------------------------------
// Generic 64x64 tile, BK=16, 256 threads, 4x4 per thread fp32 GEMM pieces
// ---------------------------------------------------------------------------

// C = A[M,K] @ W[K,N] + bias, output written in split-head layout [B,H,S,DH]
__global__ void __launch_bounds__(256) proj_split_kernel(
    const float* __restrict__ A, const float* __restrict__ W,
    const float* __restrict__ bias, float* __restrict__ out)
{
    const int K = E_DIM, N = E_DIM;
    __shared__ float As[16][64];   // As[k][m]
    __shared__ float Ws[16][64];   // Ws[k][n]
    int tid = threadIdx.x;
    int row0 = blockIdx.y * 64;
    int col0 = blockIdx.x * 64;
    int trow = tid >> 4;           // 0..15
    int tcol = tid & 15;           // 0..15
    int mA  = tid >> 2;            // 0..63
    int kqA = tid & 3;             // 0..3
    int kkW = tid >> 4;            // 0..15
    int n4W = tid & 15;            // 0..15

    float acc[4][4] = {};
    for (int k0 = 0; k0 < K; k0 += 16) {
        float4 va = *(const float4*)(A + (size_t)(row0 + mA) * K + k0 + kqA * 4);
        As[kqA * 4 + 0][mA] = va.x;
        As[kqA * 4 + 1][mA] = va.y;
        As[kqA * 4 + 2][mA] = va.z;
        As[kqA * 4 + 3][mA] = va.w;
        float4 vw = *(const float4*)(W + (size_t)(k0 + kkW) * N + col0 + n4W * 4);
        *(float4*)&Ws[kkW][n4W * 4] = vw;
        __syncthreads();
#pragma unroll
        for (int k = 0; k < 16; k++) {
            float4 av = *(const float4*)&As[k][trow * 4];
            float4 bv = *(const float4*)&Ws[k][tcol * 4];
            float a[4] = {av.x, av.y, av.z, av.w};
            float b[4] = {bv.x, bv.y, bv.z, bv.w};
#pragma unroll
            for (int i = 0; i < 4; i++)
#pragma unroll
                for (int j = 0; j < 4; j++)
                    acc[i][j] = fmaf(a[i], b[j], acc[i][j]);
        }
        __syncthreads();
    }
#pragma unroll
    for (int i = 0; i < 4; i++) {
        int m = row0 + trow * 4 + i;
        int b = m >> 11;            // / S_DIM
        int s = m & (S_DIM - 1);
#pragma unroll
        for (int j = 0; j < 4; j++) {
            int n = col0 + tcol * 4 + j;
            int h = n >> 6;
            int d = n & 63;
            out[(((size_t)(b * H_NUM + h) * S_DIM + s) << 6) + d] = acc[i][j] + bias[n];
        }
    }
}

// C = A[M,K] @ W[K,N] + bias, plain row-major output [M,N]
__global__ void __launch_bounds__(256) proj_linear_kernel(
    const float* __restrict__ A, const float* __restrict__ W,
    const float* __restrict__ bias, float* __restrict__ out)
{
    const int K = E_DIM, N = E_DIM;
    __shared__ float As[16][64];
    __shared__ float Ws[16][64];
    int tid = threadIdx.x;
    int row0 = blockIdx.y * 64;
    int col0 = blockIdx.x * 64;
    int trow = tid >> 4;
    int tcol = tid & 15;
    int mA  = tid >> 2;
    int kqA = tid & 3;
    int kkW = tid >> 4;
    int n4W = tid & 15;

    float acc[4][4] = {};
    for (int k0 = 0; k0 < K; k0 += 16) {
        float4 va = *(const float4*)(A + (size_t)(row0 + mA) * K + k0 + kqA * 4);
        As[kqA * 4 + 0][mA] = va.x;
        As[kqA * 4 + 1][mA] = va.y;
        As[kqA * 4 + 2][mA] = va.z;
        As[kqA * 4 + 3][mA] = va.w;
        float4 vw = *(const float4*)(W + (size_t)(k0 + kkW) * N + col0 + n4W * 4);
        *(float4*)&Ws[kkW][n4W * 4] = vw;
        __syncthreads();
#pragma unroll
        for (int k = 0; k < 16; k++) {
            float4 av = *(const float4*)&As[k][trow * 4];
            float4 bv = *(const float4*)&Ws[k][tcol * 4];
            float a[4] = {av.x, av.y, av.z, av.w};
            float b[4] = {bv.x, bv.y, bv.z, bv.w};
#pragma unroll
            for (int i = 0; i < 4; i++)
#pragma unroll
                for (int j = 0; j < 4; j++)
                    acc[i][j] = fmaf(a[i], b[j], acc[i][j]);
        }
        __syncthreads();
    }
#pragma unroll
    for (int i = 0; i < 4; i++) {
        int m = row0 + trow * 4 + i;
#pragma unroll
        for (int j = 0; j < 4; j++) {
            int n = col0 + tcol * 4 + j;
            out[(size_t)m * N + n] = acc[i][j] + bias[n];
        }
    }
}

// logits[z,i,j] = 0.125 * dot(Q[z,i,:], K[z,j,:]) - 1e9 * mask[b, j]
// grid: (S/64, S/64, BH)
__global__ void __launch_bounds__(256) logits_kernel(
    const float* __restrict__ Q, const float* __restrict__ Kmat,
    const float* __restrict__ mask, float* __restrict__ attn)
{
    __shared__ float Qs[16][64];   // Qs[d][i]
    __shared__ float Ks[16][64];   // Ks[d][j]
    int z = blockIdx.z;
    const float* Qb = Q + (size_t)z * S_DIM * DH_DIM;
    const float* Kb = Kmat + (size_t)z * S_DIM * DH_DIM;
    const float* mb = mask + (size_t)(z >> 4) * S_DIM;  // b = z / H_NUM
    int tid = threadIdx.x;
    int row0 = blockIdx.y * 64;
    int col0 = blockIdx.x * 64;
    int trow = tid >> 4;
    int tcol = tid & 15;
    int mL = tid >> 2;   // 0..63
    int kq = tid & 3;    // 0..3

    float acc[4][4] = {};
#pragma unroll
    for (int k0 = 0; k0 < DH_DIM; k0 += 16) {
        float4 vq = *(const float4*)(Qb + (size_t)(row0 + mL) * DH_DIM + k0 + kq * 4);
        Qs[kq * 4 + 0][mL] = vq.x;
        Qs[kq * 4 + 1][mL] = vq.y;
        Qs[kq * 4 + 2][mL] = vq.z;
        Qs[kq * 4 + 3][mL] = vq.w;
        float4 vk = *(const float4*)(Kb + (size_t)(col0 + mL) * DH_DIM + k0 + kq * 4);
        Ks[kq * 4 + 0][mL] = vk.x;
        Ks[kq * 4 + 1][mL] = vk.y;
        Ks[kq * 4 + 2][mL] = vk.z;
        Ks[kq * 4 + 3][mL] = vk.w;
        __syncthreads();
#pragma unroll
        for (int k = 0; k < 16; k++) {
            float4 av = *(const float4*)&Qs[k][trow * 4];
            float4 bv = *(const float4*)&Ks[k][tcol * 4];
            float a[4] = {av.x, av.y, av.z, av.w};
            float b[4] = {bv.x, bv.y, bv.z, bv.w};
#pragma unroll
            for (int i = 0; i < 4; i++)
#pragma unroll
                for (int j = 0; j < 4; j++)
                    acc[i][j] = fmaf(a[i], b[j], acc[i][j]);
        }
        __syncthreads();
    }
#pragma unroll
    for (int i = 0; i < 4; i++) {
        int iRow = row0 + trow * 4 + i;
        float* rowp = attn + ((size_t)z * S_DIM + iRow) * S_DIM;
#pragma unroll
        for (int j = 0; j < 4; j++) {
            int jc = col0 + tcol * 4 + j;
            rowp[jc] = acc[i][j] * 0.125f - 1e9f * mb[jc];
        }
    }
}

// in-place softmax over last dim (2048). grid (S, BH), 256 threads.
__global__ void __launch_bounds__(256) softmax_kernel(float* __restrict__ attn)
{
    float* row = attn + ((size_t)blockIdx.y * S_DIM + blockIdx.x) * S_DIM;
    int tid = threadIdx.x;
    int lane = tid & 31;
    int warp = tid >> 5;
    __shared__ float red[8];

    float4 v0 = *(float4*)(row + tid * 8);
    float4 v1 = *(float4*)(row + tid * 8 + 4);
    float vals[8] = {v0.x, v0.y, v0.z, v0.w, v1.x, v1.y, v1.z, v1.w};

    float m = vals[0];
#pragma unroll
    for (int i = 1; i < 8; i++) m = fmaxf(m, vals[i]);
#pragma unroll
    for (int o = 16; o; o >>= 1) m = fmaxf(m, __shfl_xor_sync(0xFFFFFFFFu, m, o));
    if (!lane) red[warp] = m;
    __syncthreads();
    float rowmax = red[0];
#pragma unroll
    for (int w = 1; w < 8; w++) rowmax = fmaxf(rowmax, red[w]);
    __syncthreads();

    float s = 0.f;
#pragma unroll
    for (int i = 0; i < 8; i++) {
        vals[i] = __expf(vals[i] - rowmax);
        s += vals[i];
    }
#pragma unroll
    for (int o = 16; o; o >>= 1) s += __shfl_xor_sync(0xFFFFFFFFu, s, o);
    if (!lane) red[warp] = s;
    __syncthreads();
    float tot = 0.f;
#pragma unroll
    for (int w = 0; w < 8; w++) tot += red[w];
    float inv = 1.0f / tot;

#pragma unroll
    for (int i = 0; i < 8; i++) vals[i] *= inv;
    *(float4*)(row + tid * 8)     = make_float4(vals[0], vals[1], vals[2], vals[3]);
    *(float4*)(row + tid * 8 + 4) = make_float4(vals[4], vals[5], vals[6], vals[7]);
}

// ctx[b, s, h*64 + d] = sum_j attn[z, s, j] * V[z, j, d]   (z = b*H + h)
// grid: (S/64, BH), BN=64 covers all of DH.
__global__ void __launch_bounds__(256) ctx_kernel(
    const float* __restrict__ attn, const float* __restrict__ V,
    float* __restrict__ ctx)
{
    __shared__ float As[16][64];   // As[k][i]  (k = key index chunk)
    __shared__ float Ws[16][64];   // Ws[k][d]
    int z = blockIdx.y;
    const float* Ab = attn + (size_t)z * S_DIM * S_DIM;
    const float* Vb = V + (size_t)z * S_DIM * DH_DIM;
    int tid = threadIdx.x;
    int row0 = blockIdx.x * 64;
    int trow = tid >> 4;
    int tcol = tid & 15;
    int mA  = tid >> 2;
    int kqA = tid & 3;
    int kkW = tid >> 4;
    int n4W = tid & 15;

    float acc[4][4] = {};
    for (int k0 = 0; k0 < S_DIM; k0 += 16) {
        float4 va = *(const float4*)(Ab + (size_t)(row0 + mA) * S_DIM + k0 + kqA * 4);
        As[kqA * 4 + 0][mA] = va.x;
        As[kqA * 4 + 1][mA] = va.y;
        As[kqA * 4 + 2][mA] = va.z;
        As[kqA * 4 + 3][mA] = va.w;
        float4 vw = *(const float4*)(Vb + (size_t)(k0 + kkW) * DH_DIM + n4W * 4);
        *(float4*)&Ws[kkW][n4W * 4] = vw;
        __syncthreads();
#pragma unroll
        for (int k = 0; k < 16; k++) {
            float4 av = *(const float4*)&As[k][trow * 4];
            float4 bv = *(const float4*)&Ws[k][tcol * 4];
            float a[4] = {av.x, av.y, av.z, av.w};
            float b[4] = {bv.x, bv.y, bv.z, bv.w};
#pragma unroll
            for (int i = 0; i < 4; i++)
#pragma unroll
                for (int j = 0; j < 4; j++)
                    acc[i][j] = fmaf(a[i], b[j], acc[i][j]);
        }
        __syncthreads();
    }
    int b = z >> 4;
    int h = z & 15;
#pragma unroll
    for (int i = 0; i < 4; i++) {
        int s = row0 + trow * 4 + i;
#pragma unroll
        for (int j = 0; j < 4; j++) {
            int d = tcol * 4 + j;
            ctx[(size_t)(b * S_DIM + s) * E_DIM + h * DH_DIM + d] = acc[i][j];
        }
    }
}

// ---------------------------------------------------------------------------

extern "C" void kernel_launch(void* const* d_in, const int* in_sizes, int n_in,
                              void* d_out, int out_size)
{
    const float* features = (const float*)d_in[0];
    const float* mask     = (const float*)d_in[1];
    const float* Wq = (const float*)d_in[2];
    const float* bq = (const float*)d_in[3];
    const float* Wk = (const float*)d_in[4];
    const float* bk = (const float*)d_in[5];
    const float* Wv = (const float*)d_in[6];
    const float* bv = (const float*)d_in[7];
    const float* Wo = (const float*)d_in[8];
    const float* bo = (const float*)d_in[9];
    float* out = (float*)d_out;

    float *q, *k, *v, *ctx, *attn_scratch;
    cudaGetSymbolAddress((void**)&q, g_q);
    cudaGetSymbolAddress((void**)&k, g_k);
    cudaGetSymbolAddress((void**)&v, g_v);
    cudaGetSymbolAddress((void**)&ctx, g_ctx);
    cudaGetSymbolAddress((void**)&attn_scratch, g_attn);

    const long long OUT_ELEMS  = (long long)M_ROWS * E_DIM;                 // 4,194,304
    const long long ATTN_ELEMS = (long long)BH_NUM * S_DIM * S_DIM;         // 134,217,728
    float* attn = ((long long)out_size >= OUT_ELEMS + ATTN_ELEMS)
                      ? (out + OUT_ELEMS) : attn_scratch;

    dim3 blk(256);
    dim3 gproj(E_DIM / 64, M_ROWS / 64);
    proj_split_kernel<<<gproj, blk>>>(features, Wq, bq, q);
    proj_split_kernel<<<gproj, blk>>>(features, Wk, bk, k);
    proj_split_kernel<<<gproj, blk>>>(features, Wv, bv, v);
    logits_kernel<<<dim3(S_DIM / 64, S_DIM / 64, BH_NUM), blk>>>(q, k, mask, attn);
    softmax_kernel<<<dim3(S_DIM, BH_NUM), blk>>>(attn);
    ctx_kernel<<<dim3(S_DIM / 64, BH_NUM), blk>>>(attn, v, ctx);
    proj_linear_kernel<<<gproj, blk>>>(ctx, Wo, bo, out);
}

// round 2
// speedup vs baseline: 1.0007x; 1.0007x over previous
#include <cuda_runtime.h>
#include <cstdint>
#include <cstddef>

// Problem constants (fixed shapes)
#define S_DIM 2048
#define E_DIM 1024
#define H_NUM 16
#define DH_DIM 64
#define B_NUM 2
#define BH_NUM (B_NUM * H_NUM)     // 32
#define M_ROWS (B_NUM * S_DIM)     // 4096

// Scratch (static __device__ arrays — no allocations allowed)
__device__ float g_q[(size_t)BH_NUM * S_DIM * DH_DIM];     // 16 MB
__device__ float g_k[(size_t)BH_NUM * S_DIM * DH_DIM];     // 16 MB
__device__ float g_v[(size_t)BH_NUM * S_DIM * DH_DIM];     // 16 MB
__device__ float g_ctx[(size_t)M_ROWS * E_DIM];            // 16 MB
__device__ float g_attn[(size_t)BH_NUM * S_DIM * S_DIM];   // 512 MB fallback if attn not in d_out

// ---------------------------------------------------------------------------
// Generic 64x64 tile, BK=16, 256 threads, 4x4 per thread fp32 GEMM pieces
// ---------------------------------------------------------------------------

// C = A[M,K] @ W[K,N] + bias, output written in split-head layout [B,H,S,DH]
__global__ void __launch_bounds__(256) proj_split_kernel(
    const float* __restrict__ A, const float* __restrict__ W,
    const float* __restrict__ bias, float* __restrict__ out)
{
    const int K = E_DIM, N = E_DIM;
    __shared__ float As[16][64];   // As[k][m]
    __shared__ float Ws[16][64];   // Ws[k][n]
    int tid = threadIdx.x;
    int row0 = blockIdx.y * 64;
    int col0 = blockIdx.x * 64;
    int trow = tid >> 4;           // 0..15
    int tcol = tid & 15;           // 0..15
    int mA  = tid >> 2;            // 0..63
    int kqA = tid & 3;             // 0..3
    int kkW = tid >> 4;            // 0..15
    int n4W = tid & 15;            // 0..15

    float acc[4][4] = {};
    for (int k0 = 0; k0 < K; k0 += 16) {
        float4 va = *(const float4*)(A + (size_t)(row0 + mA) * K + k0 + kqA * 4);
        As[kqA * 4 + 0][mA] = va.x;
        As[kqA * 4 + 1][mA] = va.y;
        As[kqA * 4 + 2][mA] = va.z;
        As[kqA * 4 + 3][mA] = va.w;
        float4 vw = *(const float4*)(W + (size_t)(k0 + kkW) * N + col0 + n4W * 4);
        *(float4*)&Ws[kkW][n4W * 4] = vw;
        __syncthreads();
#pragma unroll
        for (int k = 0; k < 16; k++) {
            float4 av = *(const float4*)&As[k][trow * 4];
            float4 bv = *(const float4*)&Ws[k][tcol * 4];
            float a[4] = {av.x, av.y, av.z, av.w};
            float b[4] = {bv.x, bv.y, bv.z, bv.w};
#pragma unroll
            for (int i = 0; i < 4; i++)
#pragma unroll
                for (int j = 0; j < 4; j++)
                    acc[i][j] = fmaf(a[i], b[j], acc[i][j]);
        }
        __syncthreads();
    }
#pragma unroll
    for (int i = 0; i < 4; i++) {
        int m = row0 + trow * 4 + i;
        int b = m >> 11;            // / S_DIM
        int s = m & (S_DIM - 1);
#pragma unroll
        for (int j = 0; j < 4; j++) {
            int n = col0 + tcol * 4 + j;
            int h = n >> 6;
            int d = n & 63;
            out[(((size_t)(b * H_NUM + h) * S_DIM + s) << 6) + d] = acc[i][j] + bias[n];
        }
    }
}

// C = A[M,K] @ W[K,N] + bias, plain row-major output [M,N]
__global__ void __launch_bounds__(256) proj_linear_kernel(
    const float* __restrict__ A, const float* __restrict__ W,
    const float* __restrict__ bias, float* __restrict__ out)
{
    const int K = E_DIM, N = E_DIM;
    __shared__ float As[16][64];
    __shared__ float Ws[16][64];
    int tid = threadIdx.x;
    int row0 = blockIdx.y * 64;
    int col0 = blockIdx.x * 64;
    int trow = tid >> 4;
    int tcol = tid & 15;
    int mA  = tid >> 2;
    int kqA = tid & 3;
    int kkW = tid >> 4;
    int n4W = tid & 15;

    float acc[4][4] = {};
    for (int k0 = 0; k0 < K; k0 += 16) {
        float4 va = *(const float4*)(A + (size_t)(row0 + mA) * K + k0 + kqA * 4);
        As[kqA * 4 + 0][mA] = va.x;
        As[kqA * 4 + 1][mA] = va.y;
        As[kqA * 4 + 2][mA] = va.z;
        As[kqA * 4 + 3][mA] = va.w;
        float4 vw = *(const float4*)(W + (size_t)(k0 + kkW) * N + col0 + n4W * 4);
        *(float4*)&Ws[kkW][n4W * 4] = vw;
        __syncthreads();
#pragma unroll
        for (int k = 0; k < 16; k++) {
            float4 av = *(const float4*)&As[k][trow * 4];
            float4 bv = *(const float4*)&Ws[k][tcol * 4];
            float a[4] = {av.x, av.y, av.z, av.w};
            float b[4] = {bv.x, bv.y, bv.z, bv.w};
#pragma unroll
            for (int i = 0; i < 4; i++)
#pragma unroll
                for (int j = 0; j < 4; j++)
                    acc[i][j] = fmaf(a[i], b[j], acc[i][j]);
        }
        __syncthreads();
    }
#pragma unroll
    for (int i = 0; i < 4; i++) {
        int m = row0 + trow * 4 + i;
#pragma unroll
        for (int j = 0; j < 4; j++) {
            int n = col0 + tcol * 4 + j;
            out[(size_t)m * N + n] = acc[i][j] + bias[n];
        }
    }
}

// logits[z,i,j] = 0.125 * dot(Q[z,i,:], K[z,j,:]) - 1e9 * mask[b, j]
// grid: (S/64, S/64, BH)
__global__ void __launch_bounds__(256) logits_kernel(
    const float* __restrict__ Q, const float* __restrict__ Kmat,
    const float* __restrict__ mask, float* __restrict__ attn)
{
    __shared__ float Qs[16][64];   // Qs[d][i]
    __shared__ float Ks[16][64];   // Ks[d][j]
    int z = blockIdx.z;
    const float* Qb = Q + (size_t)z * S_DIM * DH_DIM;
    const float* Kb = Kmat + (size_t)z * S_DIM * DH_DIM;
    const float* mb = mask + (size_t)(z >> 4) * S_DIM;  // b = z / H_NUM
    int tid = threadIdx.x;
    int row0 = blockIdx.y * 64;
    int col0 = blockIdx.x * 64;
    int trow = tid >> 4;
    int tcol = tid & 15;
    int mL = tid >> 2;   // 0..63
    int kq = tid & 3;    // 0..3

    float acc[4][4] = {};
#pragma unroll
    for (int k0 = 0; k0 < DH_DIM; k0 += 16) {
        float4 vq = *(const float4*)(Qb + (size_t)(row0 + mL) * DH_DIM + k0 + kq * 4);
        Qs[kq * 4 + 0][mL] = vq.x;
        Qs[kq * 4 + 1][mL] = vq.y;
        Qs[kq * 4 + 2][mL] = vq.z;
        Qs[kq * 4 + 3][mL] = vq.w;
        float4 vk = *(const float4*)(Kb + (size_t)(col0 + mL) * DH_DIM + k0 + kq * 4);
        Ks[kq * 4 + 0][mL] = vk.x;
        Ks[kq * 4 + 1][mL] = vk.y;
        Ks[kq * 4 + 2][mL] = vk.z;
        Ks[kq * 4 + 3][mL] = vk.w;
        __syncthreads();
#pragma unroll
        for (int k = 0; k < 16; k++) {
            float4 av = *(const float4*)&Qs[k][trow * 4];
            float4 bv = *(const float4*)&Ks[k][tcol * 4];
            float a[4] = {av.x, av.y, av.z, av.w};
            float b[4] = {bv.x, bv.y, bv.z, bv.w};
#pragma unroll
            for (int i = 0; i < 4; i++)
#pragma unroll
                for (int j = 0; j < 4; j++)
                    acc[i][j] = fmaf(a[i], b[j], acc[i][j]);
        }
        __syncthreads();
    }
#pragma unroll
    for (int i = 0; i < 4; i++) {
        int iRow = row0 + trow * 4 + i;
        float* rowp = attn + ((size_t)z * S_DIM + iRow) * S_DIM;
#pragma unroll
        for (int j = 0; j < 4; j++) {
            int jc = col0 + tcol * 4 + j;
            rowp[jc] = acc[i][j] * 0.125f - 1e9f * mb[jc];
        }
    }
}

// in-place softmax over last dim (2048). grid (S, BH), 256 threads.
__global__ void __launch_bounds__(256) softmax_kernel(float* __restrict__ attn)
{
    float* row = attn + ((size_t)blockIdx.y * S_DIM + blockIdx.x) * S_DIM;
    int tid = threadIdx.x;
    int lane = tid & 31;
    int warp = tid >> 5;
    __shared__ float red[8];

    float4 v0 = *(float4*)(row + tid * 8);
    float4 v1 = *(float4*)(row + tid * 8 + 4);
    float vals[8] = {v0.x, v0.y, v0.z, v0.w, v1.x, v1.y, v1.z, v1.w};

    float m = vals[0];
#pragma unroll
    for (int i = 1; i < 8; i++) m = fmaxf(m, vals[i]);
#pragma unroll
    for (int o = 16; o; o >>= 1) m = fmaxf(m, __shfl_xor_sync(0xFFFFFFFFu, m, o));
    if (!lane) red[warp] = m;
    __syncthreads();
    float rowmax = red[0];
#pragma unroll
    for (int w = 1; w < 8; w++) rowmax = fmaxf(rowmax, red[w]);
    __syncthreads();

    float s = 0.f;
#pragma unroll
    for (int i = 0; i < 8; i++) {
        vals[i] = __expf(vals[i] - rowmax);
        s += vals[i];
    }
#pragma unroll
    for (int o = 16; o; o >>= 1) s += __shfl_xor_sync(0xFFFFFFFFu, s, o);
    if (!lane) red[warp] = s;
    __syncthreads();
    float tot = 0.f;
#pragma unroll
    for (int w = 0; w < 8; w++) tot += red[w];
    float inv = 1.0f / tot;

#pragma unroll
    for (int i = 0; i < 8; i++) vals[i] *= inv;
    *(float4*)(row + tid * 8)     = make_float4(vals[0], vals[1], vals[2], vals[3]);
    *(float4*)(row + tid * 8 + 4) = make_float4(vals[4], vals[5], vals[6], vals[7]);
}

// ctx[b, s, h*64 + d] = sum_j attn[z, s, j] * V[z, j, d]   (z = b*H + h)
// grid: (S/64, BH), BN=64 covers all of DH.
__global__ void __launch_bounds__(256) ctx_kernel(
    const float* __restrict__ attn, const float* __restrict__ V,
    float* __restrict__ ctx)
{
    __shared__ float As[16][64];   // As[k][i]  (k = key index chunk)
    __shared__ float Ws[16][64];   // Ws[k][d]
    int z = blockIdx.y;
    const float* Ab = attn + (size_t)z * S_DIM * S_DIM;
    const float* Vb = V + (size_t)z * S_DIM * DH_DIM;
    int tid = threadIdx.x;
    int row0 = blockIdx.x * 64;
    int trow = tid >> 4;
    int tcol = tid & 15;
    int mA  = tid >> 2;
    int kqA = tid & 3;
    int kkW = tid >> 4;
    int n4W = tid & 15;

    float acc[4][4] = {};
    for (int k0 = 0; k0 < S_DIM; k0 += 16) {
        float4 va = *(const float4*)(Ab + (size_t)(row0 + mA) * S_DIM + k0 + kqA * 4);
        As[kqA * 4 + 0][mA] = va.x;
        As[kqA * 4 + 1][mA] = va.y;
        As[kqA * 4 + 2][mA] = va.z;
        As[kqA * 4 + 3][mA] = va.w;
        float4 vw = *(const float4*)(Vb + (size_t)(k0 + kkW) * DH_DIM + n4W * 4);
        *(float4*)&Ws[kkW][n4W * 4] = vw;
        __syncthreads();
#pragma unroll
        for (int k = 0; k < 16; k++) {
            float4 av = *(const float4*)&As[k][trow * 4];
            float4 bv = *(const float4*)&Ws[k][tcol * 4];
            float a[4] = {av.x, av.y, av.z, av.w};
            float b[4] = {bv.x, bv.y, bv.z, bv.w};
#pragma unroll
            for (int i = 0; i < 4; i++)
#pragma unroll
                for (int j = 0; j < 4; j++)
                    acc[i][j] = fmaf(a[i], b[j], acc[i][j]);
        }
        __syncthreads();
    }
    int b = z >> 4;
    int h = z & 15;
#pragma unroll
    for (int i = 0; i < 4; i++) {
        int s = row0 + trow * 4 + i;
#pragma unroll
        for (int j = 0; j < 4; j++) {
            int d = tcol * 4 + j;
            ctx[(size_t)(b * S_DIM + s) * E_DIM + h * DH_DIM + d] = acc[i][j];
        }
    }
}

// ---------------------------------------------------------------------------

extern "C" void kernel_launch(void* const* d_in, const int* in_sizes, int n_in,
                              void* d_out, int out_size)
{
    const float* features = (const float*)d_in[0];
    const float* mask     = (const float*)d_in[1];
    const float* Wq = (const float*)d_in[2];
    const float* bq = (const float*)d_in[3];
    const float* Wk = (const float*)d_in[4];
    const float* bk = (const float*)d_in[5];
    const float* Wv = (const float*)d_in[6];
    const float* bv = (const float*)d_in[7];
    const float* Wo = (const float*)d_in[8];
    const float* bo = (const float*)d_in[9];
    float* out = (float*)d_out;

    float *q, *k, *v, *ctx, *attn_scratch;
    cudaGetSymbolAddress((void**)&q, g_q);
    cudaGetSymbolAddress((void**)&k, g_k);
    cudaGetSymbolAddress((void**)&v, g_v);
    cudaGetSymbolAddress((void**)&ctx, g_ctx);
    cudaGetSymbolAddress((void**)&attn_scratch, g_attn);

    const long long OUT_ELEMS  = (long long)M_ROWS * E_DIM;                 // 4,194,304
    const long long ATTN_ELEMS = (long long)BH_NUM * S_DIM * S_DIM;         // 134,217,728
    float* attn = ((long long)out_size >= OUT_ELEMS + ATTN_ELEMS)
                      ? (out + OUT_ELEMS) : attn_scratch;

    dim3 blk(256);
    dim3 gproj(E_DIM / 64, M_ROWS / 64);
    proj_split_kernel<<<gproj, blk>>>(features, Wq, bq, q);
    proj_split_kernel<<<gproj, blk>>>(features, Wk, bk, k);
    proj_split_kernel<<<gproj, blk>>>(features, Wv, bv, v);
    logits_kernel<<<dim3(S_DIM / 64, S_DIM / 64, BH_NUM), blk>>>(q, k, mask, attn);
    softmax_kernel<<<dim3(S_DIM, BH_NUM), blk>>>(attn);
    ctx_kernel<<<dim3(S_DIM / 64, BH_NUM), blk>>>(attn, v, ctx);
    proj_linear_kernel<<<gproj, blk>>>(ctx, Wo, bo, out);
}

// round 3
// speedup vs baseline: 1.1109x; 1.1101x over previous
#include <cuda_runtime.h>
#include <cstdint>
#include <cstddef>

#define S_DIM 2048
#define E_DIM 1024
#define H_NUM 16
#define DH_DIM 64
#define B_NUM 2
#define BH_NUM (B_NUM * H_NUM)     // 32
#define M_ROWS (B_NUM * S_DIM)     // 4096

__device__ float g_q[(size_t)BH_NUM * S_DIM * DH_DIM];     // 16 MB
__device__ float g_k[(size_t)BH_NUM * S_DIM * DH_DIM];     // 16 MB
__device__ float g_v[(size_t)BH_NUM * S_DIM * DH_DIM];     // 16 MB
__device__ float g_ctx[(size_t)M_ROWS * E_DIM];            // 16 MB
__device__ float g_attn[(size_t)BH_NUM * S_DIM * S_DIM];   // 512 MB fallback

// ---------------------------------------------------------------------------
// 128x128 tile, BK=16, 256 threads, 8x8 per-thread register blocking.
// Per inner k: 64B LDS -> 64 FMA (1.0 FMA/B), matched to 128B/cyc crossbar.
// ---------------------------------------------------------------------------

#define GEMM128_BODY(A_PTR, B_PTR, K_STRIDE_A, K_DIM)                           \
    __shared__ float As[16][128];                                               \
    __shared__ float Bs[16][128];                                               \
    int tid = threadIdx.x;                                                      \
    int arow = tid >> 1, ak = (tid & 1) * 8;                                    \
    int trow = tid >> 4, tcol = tid & 15;                                       \
    float acc[8][8] = {};

// C = A[M,K] @ W[K,N] + bias, output split-head [B,H,S,DH]
__global__ void __launch_bounds__(256) proj_split128(
    const float* __restrict__ A, const float* __restrict__ W,
    const float* __restrict__ bias, float* __restrict__ out)
{
    const int K = E_DIM, N = E_DIM;
    __shared__ float As[16][128];
    __shared__ float Bs[16][128];
    int tid = threadIdx.x;
    int row0 = blockIdx.y * 128, col0 = blockIdx.x * 128;
    int arow = tid >> 1, ak = (tid & 1) * 8;
    int bk = tid >> 4, bcol = (tid & 15) * 8;
    int trow = tid >> 4, tcol = tid & 15;
    float acc[8][8] = {};

    for (int k0 = 0; k0 < K; k0 += 16) {
        const float* ap = A + (size_t)(row0 + arow) * K + k0 + ak;
        float4 a0 = *(const float4*)ap;
        float4 a1 = *(const float4*)(ap + 4);
        As[ak+0][arow]=a0.x; As[ak+1][arow]=a0.y; As[ak+2][arow]=a0.z; As[ak+3][arow]=a0.w;
        As[ak+4][arow]=a1.x; As[ak+5][arow]=a1.y; As[ak+6][arow]=a1.z; As[ak+7][arow]=a1.w;
        const float* wp = W + (size_t)(k0 + bk) * N + col0 + bcol;
        *(float4*)&Bs[bk][bcol]     = *(const float4*)wp;
        *(float4*)&Bs[bk][bcol + 4] = *(const float4*)(wp + 4);
        __syncthreads();
#pragma unroll
        for (int k = 0; k < 16; k++) {
            float a[8], b[8];
            *(float4*)a     = *(const float4*)&As[k][trow*8];
            *(float4*)(a+4) = *(const float4*)&As[k][trow*8+4];
            *(float4*)b     = *(const float4*)&Bs[k][tcol*8];
            *(float4*)(b+4) = *(const float4*)&Bs[k][tcol*8+4];
#pragma unroll
            for (int i = 0; i < 8; i++)
#pragma unroll
                for (int j = 0; j < 8; j++)
                    acc[i][j] = fmaf(a[i], b[j], acc[i][j]);
        }
        __syncthreads();
    }
    int n0 = col0 + tcol * 8;
    float bsv[8];
    *(float4*)bsv     = *(const float4*)(bias + n0);
    *(float4*)(bsv+4) = *(const float4*)(bias + n0 + 4);
    int h = n0 >> 6, d0 = n0 & 63;   // 8-col group stays within one head (64 | 8)
#pragma unroll
    for (int i = 0; i < 8; i++) {
        int m = row0 + trow * 8 + i;
        int b = m >> 11, s = m & (S_DIM - 1);
        float* p = out + (((size_t)(b * H_NUM + h) * S_DIM + s) << 6) + d0;
        *(float4*)p       = make_float4(acc[i][0]+bsv[0], acc[i][1]+bsv[1], acc[i][2]+bsv[2], acc[i][3]+bsv[3]);
        *(float4*)(p + 4) = make_float4(acc[i][4]+bsv[4], acc[i][5]+bsv[5], acc[i][6]+bsv[6], acc[i][7]+bsv[7]);
    }
}

// C = A[M,K] @ W[K,N] + bias, row-major [M,N]
__global__ void __launch_bounds__(256) proj_plain128(
    const float* __restrict__ A, const float* __restrict__ W,
    const float* __restrict__ bias, float* __restrict__ out)
{
    const int K = E_DIM, N = E_DIM;
    __shared__ float As[16][128];
    __shared__ float Bs[16][128];
    int tid = threadIdx.x;
    int row0 = blockIdx.y * 128, col0 = blockIdx.x * 128;
    int arow = tid >> 1, ak = (tid & 1) * 8;
    int bk = tid >> 4, bcol = (tid & 15) * 8;
    int trow = tid >> 4, tcol = tid & 15;
    float acc[8][8] = {};

    for (int k0 = 0; k0 < K; k0 += 16) {
        const float* ap = A + (size_t)(row0 + arow) * K + k0 + ak;
        float4 a0 = *(const float4*)ap;
        float4 a1 = *(const float4*)(ap + 4);
        As[ak+0][arow]=a0.x; As[ak+1][arow]=a0.y; As[ak+2][arow]=a0.z; As[ak+3][arow]=a0.w;
        As[ak+4][arow]=a1.x; As[ak+5][arow]=a1.y; As[ak+6][arow]=a1.z; As[ak+7][arow]=a1.w;
        const float* wp = W + (size_t)(k0 + bk) * N + col0 + bcol;
        *(float4*)&Bs[bk][bcol]     = *(const float4*)wp;
        *(float4*)&Bs[bk][bcol + 4] = *(const float4*)(wp + 4);
        __syncthreads();
#pragma unroll
        for (int k = 0; k < 16; k++) {
            float a[8], b[8];
            *(float4*)a     = *(const float4*)&As[k][trow*8];
            *(float4*)(a+4) = *(const float4*)&As[k][trow*8+4];
            *(float4*)b     = *(const float4*)&Bs[k][tcol*8];
            *(float4*)(b+4) = *(const float4*)&Bs[k][tcol*8+4];
#pragma unroll
            for (int i = 0; i < 8; i++)
#pragma unroll
                for (int j = 0; j < 8; j++)
                    acc[i][j] = fmaf(a[i], b[j], acc[i][j]);
        }
        __syncthreads();
    }
    int n0 = col0 + tcol * 8;
    float bsv[8];
    *(float4*)bsv     = *(const float4*)(bias + n0);
    *(float4*)(bsv+4) = *(const float4*)(bias + n0 + 4);
#pragma unroll
    for (int i = 0; i < 8; i++) {
        int m = row0 + trow * 8 + i;
        float* p = out + (size_t)m * N + n0;
        *(float4*)p       = make_float4(acc[i][0]+bsv[0], acc[i][1]+bsv[1], acc[i][2]+bsv[2], acc[i][3]+bsv[3]);
        *(float4*)(p + 4) = make_float4(acc[i][4]+bsv[4], acc[i][5]+bsv[5], acc[i][6]+bsv[6], acc[i][7]+bsv[7]);
    }
}

// logits[z,i,j] = 0.125 * dot(Q[z,i,:], K[z,j,:]) - 1e9 * mask[b,j]
// 128x128 tile over (i, j); K dim = 64 (4 x BK16). grid (16,16,32)
__global__ void __launch_bounds__(256) logits128(
    const float* __restrict__ Q, const float* __restrict__ Kmat,
    const float* __restrict__ mask, float* __restrict__ attn)
{
    __shared__ float Qs[16][128];
    __shared__ float Ks[16][128];
    int z = blockIdx.z;
    const float* Qb = Q + (size_t)z * S_DIM * DH_DIM;
    const float* Kb = Kmat + (size_t)z * S_DIM * DH_DIM;
    const float* mb = mask + (size_t)(z >> 4) * S_DIM;
    int tid = threadIdx.x;
    int row0 = blockIdx.y * 128, col0 = blockIdx.x * 128;
    int arow = tid >> 1, ak = (tid & 1) * 8;
    int trow = tid >> 4, tcol = tid & 15;
    float acc[8][8] = {};

#pragma unroll
    for (int k0 = 0; k0 < DH_DIM; k0 += 16) {
        const float* qp = Qb + (size_t)(row0 + arow) * DH_DIM + k0 + ak;
        float4 q0 = *(const float4*)qp;
        float4 q1 = *(const float4*)(qp + 4);
        Qs[ak+0][arow]=q0.x; Qs[ak+1][arow]=q0.y; Qs[ak+2][arow]=q0.z; Qs[ak+3][arow]=q0.w;
        Qs[ak+4][arow]=q1.x; Qs[ak+5][arow]=q1.y; Qs[ak+6][arow]=q1.z; Qs[ak+7][arow]=q1.w;
        const float* kp = Kb + (size_t)(col0 + arow) * DH_DIM + k0 + ak;
        float4 kk0 = *(const float4*)kp;
        float4 kk1 = *(const float4*)(kp + 4);
        Ks[ak+0][arow]=kk0.x; Ks[ak+1][arow]=kk0.y; Ks[ak+2][arow]=kk0.z; Ks[ak+3][arow]=kk0.w;
        Ks[ak+4][arow]=kk1.x; Ks[ak+5][arow]=kk1.y; Ks[ak+6][arow]=kk1.z; Ks[ak+7][arow]=kk1.w;
        __syncthreads();
#pragma unroll
        for (int k = 0; k < 16; k++) {
            float a[8], b[8];
            *(float4*)a     = *(const float4*)&Qs[k][trow*8];
            *(float4*)(a+4) = *(const float4*)&Qs[k][trow*8+4];
            *(float4*)b     = *(const float4*)&Ks[k][tcol*8];
            *(float4*)(b+4) = *(const float4*)&Ks[k][tcol*8+4];
#pragma unroll
            for (int i = 0; i < 8; i++)
#pragma unroll
                for (int j = 0; j < 8; j++)
                    acc[i][j] = fmaf(a[i], b[j], acc[i][j]);
        }
        __syncthreads();
    }
    int j0 = col0 + tcol * 8;
    float mv[8];
    *(float4*)mv     = *(const float4*)(mb + j0);
    *(float4*)(mv+4) = *(const float4*)(mb + j0 + 4);
#pragma unroll
    for (int i = 0; i < 8; i++) {
        int iRow = row0 + trow * 8 + i;
        float* p = attn + ((size_t)z * S_DIM + iRow) * S_DIM + j0;
        *(float4*)p = make_float4(acc[i][0]*0.125f - 1e9f*mv[0], acc[i][1]*0.125f - 1e9f*mv[1],
                                  acc[i][2]*0.125f - 1e9f*mv[2], acc[i][3]*0.125f - 1e9f*mv[3]);
        *(float4*)(p+4) = make_float4(acc[i][4]*0.125f - 1e9f*mv[4], acc[i][5]*0.125f - 1e9f*mv[5],
                                      acc[i][6]*0.125f - 1e9f*mv[6], acc[i][7]*0.125f - 1e9f*mv[7]);
    }
}

// in-place softmax over last dim (2048). grid (S, BH), 256 threads.
__global__ void __launch_bounds__(256) softmax_kernel(float* __restrict__ attn)
{
    float* row = attn + ((size_t)blockIdx.y * S_DIM + blockIdx.x) * S_DIM;
    int tid = threadIdx.x;
    int lane = tid & 31;
    int warp = tid >> 5;
    __shared__ float red[8];

    float4 v0 = *(float4*)(row + tid * 8);
    float4 v1 = *(float4*)(row + tid * 8 + 4);
    float vals[8] = {v0.x, v0.y, v0.z, v0.w, v1.x, v1.y, v1.z, v1.w};

    float m = vals[0];
#pragma unroll
    for (int i = 1; i < 8; i++) m = fmaxf(m, vals[i]);
#pragma unroll
    for (int o = 16; o; o >>= 1) m = fmaxf(m, __shfl_xor_sync(0xFFFFFFFFu, m, o));
    if (!lane) red[warp] = m;
    __syncthreads();
    float rowmax = red[0];
#pragma unroll
    for (int w = 1; w < 8; w++) rowmax = fmaxf(rowmax, red[w]);
    __syncthreads();

    float s = 0.f;
#pragma unroll
    for (int i = 0; i < 8; i++) {
        vals[i] = __expf(vals[i] - rowmax);
        s += vals[i];
    }
#pragma unroll
    for (int o = 16; o; o >>= 1) s += __shfl_xor_sync(0xFFFFFFFFu, s, o);
    if (!lane) red[warp] = s;
    __syncthreads();
    float tot = 0.f;
#pragma unroll
    for (int w = 0; w < 8; w++) tot += red[w];
    float inv = 1.0f / tot;

#pragma unroll
    for (int i = 0; i < 8; i++) vals[i] *= inv;
    *(float4*)(row + tid * 8)     = make_float4(vals[0], vals[1], vals[2], vals[3]);
    *(float4*)(row + tid * 8 + 4) = make_float4(vals[4], vals[5], vals[6], vals[7]);
}

// ctx[b,s,h*64+d] = sum_j attn[z,s,j] * V[z,j,d]
// 256x64 tile, 256 threads (32x8), 8x8 per thread. grid (8, 32)
__global__ void __launch_bounds__(256) ctx256(
    const float* __restrict__ attn, const float* __restrict__ V,
    float* __restrict__ ctx)
{
    __shared__ float As[16][256];
    __shared__ float Vs[16][64];
    int z = blockIdx.y;
    const float* Ab = attn + (size_t)z * S_DIM * S_DIM;
    const float* Vb = V + (size_t)z * S_DIM * DH_DIM;
    int tid = threadIdx.x;
    int row0 = blockIdx.x * 256;
    int vk = tid >> 4, vcol = (tid & 15) * 4;
    int trow = tid >> 3, tcol = tid & 7;
    float acc[8][8] = {};

    for (int k0 = 0; k0 < S_DIM; k0 += 16) {
        const float* ap = Ab + (size_t)(row0 + tid) * S_DIM + k0;
        float4 x0 = *(const float4*)ap;
        float4 x1 = *(const float4*)(ap + 4);
        float4 x2 = *(const float4*)(ap + 8);
        float4 x3 = *(const float4*)(ap + 12);
        As[0][tid]=x0.x;  As[1][tid]=x0.y;  As[2][tid]=x0.z;  As[3][tid]=x0.w;
        As[4][tid]=x1.x;  As[5][tid]=x1.y;  As[6][tid]=x1.z;  As[7][tid]=x1.w;
        As[8][tid]=x2.x;  As[9][tid]=x2.y;  As[10][tid]=x2.z; As[11][tid]=x2.w;
        As[12][tid]=x3.x; As[13][tid]=x3.y; As[14][tid]=x3.z; As[15][tid]=x3.w;
        *(float4*)&Vs[vk][vcol] = *(const float4*)(Vb + (size_t)(k0 + vk) * DH_DIM + vcol);
        __syncthreads();
#pragma unroll
        for (int k = 0; k < 16; k++) {
            float a[8], b[8];
            *(float4*)a     = *(const float4*)&As[k][trow*8];
            *(float4*)(a+4) = *(const float4*)&As[k][trow*8+4];
            *(float4*)b     = *(const float4*)&Vs[k][tcol*8];
            *(float4*)(b+4) = *(const float4*)&Vs[k][tcol*8+4];
#pragma unroll
            for (int i = 0; i < 8; i++)
#pragma unroll
                for (int j = 0; j < 8; j++)
                    acc[i][j] = fmaf(a[i], b[j], acc[i][j]);
        }
        __syncthreads();
    }
    int b = z >> 4, h = z & 15;
    int d0 = tcol * 8;
#pragma unroll
    for (int i = 0; i < 8; i++) {
        int s = row0 + trow * 8 + i;
        float* p = ctx + (size_t)(b * S_DIM + s) * E_DIM + h * DH_DIM + d0;
        *(float4*)p       = make_float4(acc[i][0], acc[i][1], acc[i][2], acc[i][3]);
        *(float4*)(p + 4) = make_float4(acc[i][4], acc[i][5], acc[i][6], acc[i][7]);
    }
}

// ---------------------------------------------------------------------------

extern "C" void kernel_launch(void* const* d_in, const int* in_sizes, int n_in,
                              void* d_out, int out_size)
{
    const float* features = (const float*)d_in[0];
    const float* mask     = (const float*)d_in[1];
    const float* Wq = (const float*)d_in[2];
    const float* bq = (const float*)d_in[3];
    const float* Wk = (const float*)d_in[4];
    const float* bk = (const float*)d_in[5];
    const float* Wv = (const float*)d_in[6];
    const float* bv = (const float*)d_in[7];
    const float* Wo = (const float*)d_in[8];
    const float* bo = (const float*)d_in[9];
    float* out = (float*)d_out;

    float *q, *k, *v, *ctx, *attn_scratch;
    cudaGetSymbolAddress((void**)&q, g_q);
    cudaGetSymbolAddress((void**)&k, g_k);
    cudaGetSymbolAddress((void**)&v, g_v);
    cudaGetSymbolAddress((void**)&ctx, g_ctx);
    cudaGetSymbolAddress((void**)&attn_scratch, g_attn);

    const long long OUT_ELEMS  = (long long)M_ROWS * E_DIM;
    const long long ATTN_ELEMS = (long long)BH_NUM * S_DIM * S_DIM;
    float* attn = ((long long)out_size >= OUT_ELEMS + ATTN_ELEMS)
                      ? (out + OUT_ELEMS) : attn_scratch;

    dim3 blk(256);
    dim3 gproj(E_DIM / 128, M_ROWS / 128);   // (8, 32)
    proj_split128<<<gproj, blk>>>(features, Wq, bq, q);
    proj_split128<<<gproj, blk>>>(features, Wk, bk, k);
    proj_split128<<<gproj, blk>>>(features, Wv, bv, v);
    logits128<<<dim3(S_DIM / 128, S_DIM / 128, BH_NUM), blk>>>(q, k, mask, attn);
    softmax_kernel<<<dim3(S_DIM, BH_NUM), blk>>>(attn);
    ctx256<<<dim3(S_DIM / 256, BH_NUM), blk>>>(attn, v, ctx);
    proj_plain128<<<gproj, blk>>>(ctx, Wo, bo, out);
}

// round 5
// speedup vs baseline: 1.6352x; 1.4720x over previous
#include <cuda_runtime.h>
#include <cuda_bf16.h>
#include <cstdint>
#include <cstddef>

#define S_DIM 2048
#define E_DIM 1024
#define H_NUM 16
#define DH_DIM 64
#define B_NUM 2
#define BH_NUM (B_NUM * H_NUM)     // 32
#define M_ROWS (B_NUM * S_DIM)     // 4096

__device__ float g_q[(size_t)BH_NUM * S_DIM * DH_DIM];     // [z,s,d]
__device__ float g_k[(size_t)BH_NUM * S_DIM * DH_DIM];     // [z,s,d]
__device__ float g_vt[(size_t)BH_NUM * DH_DIM * S_DIM];    // [z,d,s]
__device__ float g_ctx[(size_t)M_ROWS * E_DIM];
__device__ float g_attn[(size_t)BH_NUM * S_DIM * S_DIM];   // fallback

// ---------------------------------------------------------------------------
// helpers
// ---------------------------------------------------------------------------
__device__ __forceinline__ uint32_t smem_u32(const void* p) {
    uint32_t a;
    asm("{ .reg .u64 t; cvta.to.shared.u64 t, %1; cvt.u32.u64 %0, t; }" : "=r"(a) : "l"(p));
    return a;
}
__device__ __forceinline__ uint32_t sw32(uint32_t boff) {
    return boff ^ ((boff >> 3) & 0x70);   // SW128 swizzle, 16B granules
}
__device__ __forceinline__ void ldm4(uint32_t* r, uint32_t a) {
    asm volatile("ldmatrix.sync.aligned.m8n8.x4.shared.b16 {%0,%1,%2,%3}, [%4];"
        : "=r"(r[0]), "=r"(r[1]), "=r"(r[2]), "=r"(r[3]) : "r"(a));
}
__device__ __forceinline__ void mma_bf16(float* c, const uint32_t* a, uint32_t b0, uint32_t b1) {
    asm volatile(
        "mma.sync.aligned.m16n8k16.row.col.f32.bf16.bf16.f32 "
        "{%0,%1,%2,%3}, {%4,%5,%6,%7}, {%8,%9}, {%0,%1,%2,%3};"
        : "+f"(c[0]), "+f"(c[1]), "+f"(c[2]), "+f"(c[3])
        : "r"(a[0]), "r"(a[1]), "r"(a[2]), "r"(a[3]), "r"(b0), "r"(b1));
}

// ---------------------------------------------------------------------------
// Tile loaders: fp32 gmem -> bf16 hi/lo, SW128-swizzled K-major smem (128B rows)
// ---------------------------------------------------------------------------
__device__ __forceinline__ void split8(const float* v, uint32_t* hi, uint32_t* lo) {
#pragma unroll
    for (int q = 0; q < 4; q++) {
        __nv_bfloat16 h0 = __float2bfloat16(v[2*q]);
        __nv_bfloat16 h1 = __float2bfloat16(v[2*q+1]);
        __nv_bfloat16 l0 = __float2bfloat16(v[2*q]   - __bfloat162float(h0));
        __nv_bfloat16 l1 = __float2bfloat16(v[2*q+1] - __bfloat162float(h1));
        hi[q] = (uint32_t)__bfloat16_as_ushort(h0) | ((uint32_t)__bfloat16_as_ushort(h1) << 16);
        lo[q] = (uint32_t)__bfloat16_as_ushort(l0) | ((uint32_t)__bfloat16_as_ushort(l1) << 16);
    }
}

// 128 rows x 64 cols fp32 -> hi/lo bf16 tiles
__device__ __forceinline__ void load_t128(const float* g, int ld, char* sm,
                                          int ohi, int olo, int tid) {
    int row = tid >> 1;
    int c0  = (tid & 1) * 32;
    const float* p = g + (size_t)row * ld + c0;
#pragma unroll
    for (int gi = 0; gi < 4; gi++) {
        float v[8];
        *(float4*)(v)     = *(const float4*)(p + gi * 8);
        *(float4*)(v + 4) = *(const float4*)(p + gi * 8 + 4);
        uint32_t hi[4], lo[4];
        split8(v, hi, lo);
        uint32_t sw = sw32(row * 128 + (c0 + gi * 8) * 2);
        *(uint4*)(sm + ohi + sw) = make_uint4(hi[0], hi[1], hi[2], hi[3]);
        *(uint4*)(sm + olo + sw) = make_uint4(lo[0], lo[1], lo[2], lo[3]);
    }
}

// 64 rows x 64 cols
__device__ __forceinline__ void load_t64(const float* g, int ld, char* sm,
                                         int ohi, int olo, int tid) {
    int row = tid >> 2;
    int c0  = (tid & 3) * 16;
    const float* p = g + (size_t)row * ld + c0;
#pragma unroll
    for (int gi = 0; gi < 2; gi++) {
        float v[8];
        *(float4*)(v)     = *(const float4*)(p + gi * 8);
        *(float4*)(v + 4) = *(const float4*)(p + gi * 8 + 4);
        uint32_t hi[4], lo[4];
        split8(v, hi, lo);
        uint32_t sw = sw32(row * 128 + (c0 + gi * 8) * 2);
        *(uint4*)(sm + ohi + sw) = make_uint4(hi[0], hi[1], hi[2], hi[3]);
        *(uint4*)(sm + olo + sw) = make_uint4(lo[0], lo[1], lo[2], lo[3]);
    }
}

// W^T tile: dest rows n (128) x cols k (64); src W[k0+k][n0+n]
__device__ __forceinline__ void load_wt(const float* W, int n0, int k0, char* sm,
                                        int ohi, int olo, int tid) {
#pragma unroll
    for (int it = 0; it < 16; it++) {
        int idx = tid + 256 * it;
        int n = idx & 127;
        int kp = idx >> 7;  // 0..31
        const float* wp = W + (size_t)(k0 + 2 * kp) * E_DIM + n0 + n;
        float w0 = wp[0], w1 = wp[E_DIM];
        __nv_bfloat16 h0 = __float2bfloat16(w0);
        __nv_bfloat16 h1 = __float2bfloat16(w1);
        __nv_bfloat16 l0 = __float2bfloat16(w0 - __bfloat162float(h0));
        __nv_bfloat16 l1 = __float2bfloat16(w1 - __bfloat162float(h1));
        uint32_t hv = (uint32_t)__bfloat16_as_ushort(h0) | ((uint32_t)__bfloat16_as_ushort(h1) << 16);
        uint32_t lv = (uint32_t)__bfloat16_as_ushort(l0) | ((uint32_t)__bfloat16_as_ushort(l1) << 16);
        uint32_t sw = sw32(n * 128 + kp * 4);
        *(uint32_t*)(sm + ohi + sw) = hv;
        *(uint32_t*)(sm + olo + sw) = lv;
    }
}

// ---------------------------------------------------------------------------
// Warp compute: one 64-K chunk. Warp tile = 32 (m) x (NH*16) (n).
// acc layout: acc[mt*2*NH + nt][4], nt = n8-tile index.
// hh + hl + lh MMAs (Markidis split).
// ---------------------------------------------------------------------------
template <int NH>
__device__ __forceinline__ void compute_chunk(
    uint32_t sa_hi, uint32_t sa_lo, uint32_t sb_hi, uint32_t sb_lo,
    int m0w, int n0w, int lane, float (*acc)[4])
{
    int lrow = lane & 7, grp = lane >> 3;
#pragma unroll
    for (int ks = 0; ks < 4; ks++) {
        int k = ks * 16;
        uint32_t ah[2][4], al[2][4];
#pragma unroll
        for (int mt = 0; mt < 2; mt++) {
            int row = m0w + mt * 16 + lrow + (grp & 1) * 8;
            int col = k + (grp >> 1) * 8;
            uint32_t off = sw32(row * 128 + col * 2);
            ldm4(ah[mt], sa_hi + off);
            ldm4(al[mt], sa_lo + off);
        }
#pragma unroll
        for (int nh = 0; nh < NH; nh++) {
            int rowb = n0w + nh * 16 + lrow + ((grp >> 1) & 1) * 8;
            int colb = k + (grp & 1) * 8;
            uint32_t offb = sw32(rowb * 128 + colb * 2);
            uint32_t bh[4], bl[4];
            ldm4(bh, sb_hi + offb);
            ldm4(bl, sb_lo + offb);
#pragma unroll
            for (int mt = 0; mt < 2; mt++) {
                float* c0 = acc[mt * 2 * NH + nh * 2];
                float* c1 = acc[mt * 2 * NH + nh * 2 + 1];
                mma_bf16(c0, ah[mt], bh[0], bh[1]);
                mma_bf16(c1, ah[mt], bh[2], bh[3]);
                mma_bf16(c0, ah[mt], bl[0], bl[1]);
                mma_bf16(c1, ah[mt], bl[2], bl[3]);
                mma_bf16(c0, al[mt], bh[0], bh[1]);
                mma_bf16(c1, al[mt], bh[2], bh[3]);
            }
        }
    }
}

// ---------------------------------------------------------------------------
// Projection GEMM: C = A[4096,1024] @ W[1024,1024] + bias
// mode 0: split-head [z,s,d]; mode 1: transposed V [z,d,s]; mode 2: plain [m,n]
// grid (8, 32), 256 threads, smem 128KB double-buffered.
// ---------------------------------------------------------------------------
#define PROJ_SMEM (2 * 65536)
__global__ void __launch_bounds__(256) proj_mma(
    const float* __restrict__ A, const float* __restrict__ W,
    const float* __restrict__ bias, float* __restrict__ out, int mode)
{
    extern __shared__ char sm[];
    uint32_t sb = smem_u32(sm);
    int tid = threadIdx.x, lane = tid & 31, wid = tid >> 5;
    int warp_m = wid & 3, warp_n = wid >> 2;
    int n0 = blockIdx.x * 128, m0 = blockIdx.y * 128;

    float acc[16][4] = {};
    load_t128(A + (size_t)m0 * E_DIM, E_DIM, sm, 0, 16384, tid);
    load_wt(W, n0, 0, sm, 32768, 49152, tid);
    __syncthreads();

    for (int c = 0; c < 16; c++) {
        int cur = (c & 1) * 65536;
        if (c < 15) {
            int nb = ((c + 1) & 1) * 65536;
            load_t128(A + (size_t)m0 * E_DIM + (c + 1) * 64, E_DIM, sm, nb, nb + 16384, tid);
            load_wt(W, n0, (c + 1) * 64, sm, nb + 32768, nb + 49152, tid);
        }
        compute_chunk<4>(sb + cur, sb + cur + 16384, sb + cur + 32768, sb + cur + 49152,
                         warp_m * 32, warp_n * 64, lane, acc);
        __syncthreads();
    }

    int crow = lane >> 2, cc = (lane & 3) * 2;
#pragma unroll
    for (int mt = 0; mt < 2; mt++) {
#pragma unroll
        for (int t8 = 0; t8 < 8; t8++) {
            const float* c = acc[mt * 8 + t8];
            int n = n0 + warp_n * 64 + t8 * 8 + cc;
            int r0 = m0 + warp_m * 32 + mt * 16 + crow;
            float b0 = bias[n], b1 = bias[n + 1];
            if (mode == 2) {
                *(float2*)(out + (size_t)r0 * E_DIM + n)       = make_float2(c[0] + b0, c[1] + b1);
                *(float2*)(out + (size_t)(r0 + 8) * E_DIM + n) = make_float2(c[2] + b0, c[3] + b1);
            } else if (mode == 0) {
                int h = n >> 6, d = n & 63;
#pragma unroll
                for (int rr = 0; rr < 2; rr++) {
                    int m = r0 + rr * 8;
                    int b = m >> 11, s = m & (S_DIM - 1);
                    float* p = out + (((size_t)(b * H_NUM + h) * S_DIM + s) << 6) + d;
                    *(float2*)p = make_float2(c[2 * rr] + b0, c[2 * rr + 1] + b1);
                }
            } else {
                int h = n >> 6, d = n & 63;
#pragma unroll
                for (int rr = 0; rr < 2; rr++) {
                    int m = r0 + rr * 8;
                    int b = m >> 11, s = m & (S_DIM - 1);
                    size_t base = ((size_t)(b * H_NUM + h) * DH_DIM + d) * S_DIM + s;
                    out[base]         = c[2 * rr] + b0;
                    out[base + S_DIM] = c[2 * rr + 1] + b1;
                }
            }
        }
    }
}

// ---------------------------------------------------------------------------
// Logits: attn[z,i,j] = 0.125 * Q[z,i,:]·K[z,j,:] - 1e9*mask[b,j]
// grid (16, 16, 32), 256 threads, single K=64 chunk, smem 64KB.
// ---------------------------------------------------------------------------
#define LOG_SMEM 65536
__global__ void __launch_bounds__(256) logits_mma(
    const float* __restrict__ Q, const float* __restrict__ Kmat,
    const float* __restrict__ mask, float* __restrict__ attn)
{
    extern __shared__ char sm[];
    uint32_t sb = smem_u32(sm);
    int tid = threadIdx.x, lane = tid & 31, wid = tid >> 5;
    int warp_m = wid & 3, warp_n = wid >> 2;
    int z = blockIdx.z;
    int i0 = blockIdx.y * 128, j0 = blockIdx.x * 128;
    const float* Qb = Q + (size_t)z * S_DIM * DH_DIM;
    const float* Kb = Kmat + (size_t)z * S_DIM * DH_DIM;
    const float* mb = mask + (size_t)(z >> 4) * S_DIM;

    load_t128(Qb + (size_t)i0 * DH_DIM, DH_DIM, sm, 0, 16384, tid);
    load_t128(Kb + (size_t)j0 * DH_DIM, DH_DIM, sm, 32768, 49152, tid);
    __syncthreads();

    float acc[16][4] = {};
    compute_chunk<4>(sb, sb + 16384, sb + 32768, sb + 49152,
                     warp_m * 32, warp_n * 64, lane, acc);

    int crow = lane >> 2, cc = (lane & 3) * 2;
#pragma unroll
    for (int mt = 0; mt < 2; mt++) {
#pragma unroll
        for (int t8 = 0; t8 < 8; t8++) {
            const float* c = acc[mt * 8 + t8];
            int j = j0 + warp_n * 64 + t8 * 8 + cc;
            int i = i0 + warp_m * 32 + mt * 16 + crow;
            float m0v = 1e9f * mb[j], m1v = 1e9f * mb[j + 1];
            *(float2*)(attn + ((size_t)z * S_DIM + i) * S_DIM + j) =
                make_float2(c[0] * 0.125f - m0v, c[1] * 0.125f - m1v);
            *(float2*)(attn + ((size_t)z * S_DIM + i + 8) * S_DIM + j) =
                make_float2(c[2] * 0.125f - m0v, c[3] * 0.125f - m1v);
        }
    }
}

// ---------------------------------------------------------------------------
// ctx[b,s,h*64+d] = sum_j attn[z,s,j] * vT[z,d,j]; M=128, N=64, K=2048
// grid (16, 32), 256 threads, smem 96KB double-buffered.
// ---------------------------------------------------------------------------
#define CTX_SMEM (2 * 49152)
__global__ void __launch_bounds__(256) ctx_mma(
    const float* __restrict__ attn, const float* __restrict__ vT,
    float* __restrict__ ctx)
{
    extern __shared__ char sm[];
    uint32_t sb = smem_u32(sm);
    int tid = threadIdx.x, lane = tid & 31, wid = tid >> 5;
    int warp_m = wid & 3, warp_n = wid >> 2;
    int z = blockIdx.y, i0 = blockIdx.x * 128;
    const float* Ab = attn + ((size_t)z * S_DIM + i0) * S_DIM;
    const float* Vb = vT + (size_t)z * DH_DIM * S_DIM;

    float acc[8][4] = {};
    load_t128(Ab, S_DIM, sm, 0, 16384, tid);
    load_t64(Vb, S_DIM, sm, 32768, 40960, tid);
    __syncthreads();

    for (int c = 0; c < 32; c++) {
        int cur = (c & 1) * 49152;
        if (c < 31) {
            int nb = ((c + 1) & 1) * 49152;
            load_t128(Ab + (c + 1) * 64, S_DIM, sm, nb, nb + 16384, tid);
            load_t64(Vb + (c + 1) * 64, S_DIM, sm, nb + 32768, nb + 40960, tid);
        }
        compute_chunk<2>(sb + cur, sb + cur + 16384, sb + cur + 32768, sb + cur + 40960,
                         warp_m * 32, warp_n * 32, lane, acc);
        __syncthreads();
    }

    int b = z >> 4, h = z & 15;
    int crow = lane >> 2, cc = (lane & 3) * 2;
#pragma unroll
    for (int mt = 0; mt < 2; mt++) {
#pragma unroll
        for (int t8 = 0; t8 < 4; t8++) {
            const float* c = acc[mt * 4 + t8];
            int d = warp_n * 32 + t8 * 8 + cc;
            int s0 = i0 + warp_m * 32 + mt * 16 + crow;
            float* p0 = ctx + (size_t)(b * S_DIM + s0) * E_DIM + h * DH_DIM + d;
            float* p1 = ctx + (size_t)(b * S_DIM + s0 + 8) * E_DIM + h * DH_DIM + d;
            *(float2*)p0 = make_float2(c[0], c[1]);
            *(float2*)p1 = make_float2(c[2], c[3]);
        }
    }
}

// ---------------------------------------------------------------------------
// softmax: in-place over last dim. grid (S, BH), 256 threads.
// ---------------------------------------------------------------------------
__global__ void __launch_bounds__(256) softmax_kernel(float* __restrict__ attn)
{
    float* row = attn + ((size_t)blockIdx.y * S_DIM + blockIdx.x) * S_DIM;
    int tid = threadIdx.x;
    int lane = tid & 31;
    int warp = tid >> 5;
    __shared__ float red[8];

    float4 v0 = *(float4*)(row + tid * 8);
    float4 v1 = *(float4*)(row + tid * 8 + 4);
    float vals[8] = {v0.x, v0.y, v0.z, v0.w, v1.x, v1.y, v1.z, v1.w};

    float m = vals[0];
#pragma unroll
    for (int i = 1; i < 8; i++) m = fmaxf(m, vals[i]);
#pragma unroll
    for (int o = 16; o; o >>= 1) m = fmaxf(m, __shfl_xor_sync(0xFFFFFFFFu, m, o));
    if (!lane) red[warp] = m;
    __syncthreads();
    float rowmax = red[0];
#pragma unroll
    for (int w = 1; w < 8; w++) rowmax = fmaxf(rowmax, red[w]);
    __syncthreads();

    float s = 0.f;
#pragma unroll
    for (int i = 0; i < 8; i++) {
        vals[i] = __expf(vals[i] - rowmax);
        s += vals[i];
    }
#pragma unroll
    for (int o = 16; o; o >>= 1) s += __shfl_xor_sync(0xFFFFFFFFu, s, o);
    if (!lane) red[warp] = s;
    __syncthreads();
    float tot = 0.f;
#pragma unroll
    for (int w = 0; w < 8; w++) tot += red[w];
    float inv = 1.0f / tot;

#pragma unroll
    for (int i = 0; i < 8; i++) vals[i] *= inv;
    *(float4*)(row + tid * 8)     = make_float4(vals[0], vals[1], vals[2], vals[3]);
    *(float4*)(row + tid * 8 + 4) = make_float4(vals[4], vals[5], vals[6], vals[7]);
}

// ---------------------------------------------------------------------------

extern "C" void kernel_launch(void* const* d_in, const int* in_sizes, int n_in,
                              void* d_out, int out_size)
{
    const float* features = (const float*)d_in[0];
    const float* mask     = (const float*)d_in[1];
    const float* Wq = (const float*)d_in[2];
    const float* bq = (const float*)d_in[3];
    const float* Wk = (const float*)d_in[4];
    const float* bk = (const float*)d_in[5];
    const float* Wv = (const float*)d_in[6];
    const float* bv = (const float*)d_in[7];
    const float* Wo = (const float*)d_in[8];
    const float* bo = (const float*)d_in[9];
    float* out = (float*)d_out;

    float *q, *k, *vt, *ctx, *attn_scratch;
    cudaGetSymbolAddress((void**)&q, g_q);
    cudaGetSymbolAddress((void**)&k, g_k);
    cudaGetSymbolAddress((void**)&vt, g_vt);
    cudaGetSymbolAddress((void**)&ctx, g_ctx);
    cudaGetSymbolAddress((void**)&attn_scratch, g_attn);

    const long long OUT_ELEMS  = (long long)M_ROWS * E_DIM;
    const long long ATTN_ELEMS = (long long)BH_NUM * S_DIM * S_DIM;
    float* attn = ((long long)out_size >= OUT_ELEMS + ATTN_ELEMS)
                      ? (out + OUT_ELEMS) : attn_scratch;

    cudaFuncSetAttribute(proj_mma, cudaFuncAttributeMaxDynamicSharedMemorySize, PROJ_SMEM);
    cudaFuncSetAttribute(logits_mma, cudaFuncAttributeMaxDynamicSharedMemorySize, LOG_SMEM);
    cudaFuncSetAttribute(ctx_mma, cudaFuncAttributeMaxDynamicSharedMemorySize, CTX_SMEM);

    dim3 blk(256);
    dim3 gproj(E_DIM / 128, M_ROWS / 128);   // (8, 32)
    proj_mma<<<gproj, blk, PROJ_SMEM>>>(features, Wq, bq, q, 0);
    proj_mma<<<gproj, blk, PROJ_SMEM>>>(features, Wk, bk, k, 0);
    proj_mma<<<gproj, blk, PROJ_SMEM>>>(features, Wv, bv, vt, 1);
    logits_mma<<<dim3(S_DIM / 128, S_DIM / 128, BH_NUM), blk, LOG_SMEM>>>(q, k, mask, attn);
    softmax_kernel<<<dim3(S_DIM, BH_NUM), blk>>>(attn);
    ctx_mma<<<dim3(S_DIM / 128, BH_NUM), blk, CTX_SMEM>>>(attn, vt, ctx);
    proj_mma<<<gproj, blk, PROJ_SMEM>>>(ctx, Wo, bo, out, 2);
}